// round 11
// baseline (speedup 1.0000x reference)
#include <cuda_runtime.h>
#include <cuda_bf16.h>
#include <cstdint>

// ============================================================================
// KAN FFN via mma.sync (HMMA) bf16, 2-term split, ldmatrix, double-buffered.
//
// R11 vs R10 (723us):
//  - MMA block issued BEFORE next-chunk fill: featurize FMAs + cp.asyncs now
//    issue while the tensor pipe drains the queued MMAs (in-order issue was
//    serializing fill ahead of MMAs each chunk -> tensor idle in fill phase).
//  - Split passes reordered pass-outer within each ntp block: consecutive
//    MMAs hit different accumulators (4-way ILP vs 2 chained).
// ============================================================================

#define D1 1024
#define H1 128
#define MAXROWS 16384
#define PADW 20                   // words per 32-feat row (16 data + 4 pad)
#define PB   (128 * PADW * 4)     // plane bytes (10240)
#define SB   (4 * PB)             // stage bytes  (40960): Ah|Al|Bh|Bl

__device__ __nv_bfloat16 g_W1h[H1 * D1 * 8];
__device__ __nv_bfloat16 g_W1l[H1 * D1 * 8];
__device__ __nv_bfloat16 g_W2h[D1 * H1 * 8];
__device__ __nv_bfloat16 g_W2l[D1 * H1 * 8];
__device__ float g_y1p[2 * MAXROWS * H1];
__device__ __nv_bfloat16 g_A2h[MAXROWS * H1 * 8];
__device__ __nv_bfloat16 g_A2l[MAXROWS * H1 * 8];

// ---------------- KAN featurization (verified R1) ---------------------------
__device__ __forceinline__ void kan_feats(float x, float* f) {
    const float h = 2.0f / 3.0f;
    float B[9];
#pragma unroll
    for (int t = 0; t < 9; ++t) {
        float gl = (float)(t - 3) * h - 1.0f;
        float gr = (float)(t - 2) * h - 1.0f;
        B[t] = (x >= gl && x < gr) ? 1.0f : 0.0f;
    }
#pragma unroll
    for (int d = 1; d <= 3; ++d) {
#pragma unroll
        for (int t = 0; t + d < 9; ++t) {
            float g_t   = (float)(t - 3) * h - 1.0f;
            float g_t1  = (float)(t - 2) * h - 1.0f;
            float g_td  = (float)(t + d - 3) * h - 1.0f;
            float g_td1 = (float)(t + d - 2) * h - 1.0f;
            float inv_l = 1.0f / (g_td - g_t);
            float inv_r = 1.0f / (g_td1 - g_t1);
            B[t] = (x - g_t) * inv_l * B[t] + (g_td1 - x) * inv_r * B[t + 1];
        }
    }
    float sig = 1.0f / (1.0f + __expf(-x));
    f[0] = x * sig;
#pragma unroll
    for (int t = 0; t < 6; ++t) f[1 + t] = B[t];
}

__device__ __forceinline__ uint32_t split_pair(float a, float b, uint32_t& lo) {
    __nv_bfloat16 ah = __float2bfloat16(a), bh = __float2bfloat16(b);
    __nv_bfloat16 al = __float2bfloat16(a - __bfloat162float(ah));
    __nv_bfloat16 bl = __float2bfloat16(b - __bfloat162float(bh));
    lo = (uint32_t)__bfloat16_as_ushort(al) | ((uint32_t)__bfloat16_as_ushort(bl) << 16);
    return (uint32_t)__bfloat16_as_ushort(ah) | ((uint32_t)__bfloat16_as_ushort(bh) << 16);
}

__device__ __forceinline__ void mma16816(float* d, const uint32_t* a,
                                         uint32_t b0, uint32_t b1) {
    asm volatile(
        "mma.sync.aligned.m16n8k16.row.col.f32.bf16.bf16.f32 "
        "{%0,%1,%2,%3}, {%4,%5,%6,%7}, {%8,%9}, {%0,%1,%2,%3};"
        : "+f"(d[0]), "+f"(d[1]), "+f"(d[2]), "+f"(d[3])
        : "r"(a[0]), "r"(a[1]), "r"(a[2]), "r"(a[3]), "r"(b0), "r"(b1));
}

__device__ __forceinline__ void ldm_x4(uint32_t* r, uint32_t addr) {
    asm volatile("ldmatrix.sync.aligned.m8n8.x4.shared.b16 {%0,%1,%2,%3}, [%4];"
                 : "=r"(r[0]), "=r"(r[1]), "=r"(r[2]), "=r"(r[3]) : "r"(addr));
}

__device__ __forceinline__ void cp_async16(uint32_t dst, const void* src) {
    asm volatile("cp.async.cg.shared.global [%0], [%1], 16;"
                 :: "r"(dst), "l"(src) : "memory");
}
__device__ __forceinline__ void cp_commit() {
    asm volatile("cp.async.commit_group;" ::: "memory");
}
__device__ __forceinline__ void cp_wait0() {
    asm volatile("cp.async.wait_group 0;" ::: "memory");
}

// ---------------- Weight prep (unchanged) -----------------------------------
template <int IN, int OUT>
__global__ void prep_wt(const float* __restrict__ coef,
                        const float* __restrict__ sb,
                        const float* __restrict__ sp,
                        __nv_bfloat16* __restrict__ Whi,
                        __nv_bfloat16* __restrict__ Wlo) {
    int idx = blockIdx.x * blockDim.x + threadIdx.x;
    if (idx >= IN * OUT) return;
    int i = idx / OUT, o = idx - i * OUT;
    float vals[8];
    vals[0] = sb[idx];
    float s = sp[idx];
#pragma unroll
    for (int g = 0; g < 6; ++g) vals[1 + g] = coef[(size_t)idx * 6 + g] * s;
    vals[7] = 0.0f;
    size_t base = (size_t)o * (IN * 8) + (size_t)i * 8;
#pragma unroll
    for (int c = 0; c < 8; ++c) {
        float f = vals[c];
        __nv_bfloat16 hb = __float2bfloat16(f);
        Whi[base + c] = hb;
        Wlo[base + c] = __float2bfloat16(f - __bfloat162float(hb));
    }
}

// ---------------- feat2 (unchanged) -----------------------------------------
__global__ void feat2(const float* __restrict__ p0, const float* __restrict__ p1,
                      __nv_bfloat16* __restrict__ A2h,
                      __nv_bfloat16* __restrict__ A2l, int total) {
    int idx = blockIdx.x * blockDim.x + threadIdx.x;
    if (idx >= total) return;
    float y = p0[idx] + p1[idx];
    float f[7];
    kan_feats(y, f);
    uint4 hv, lv;
    uint32_t* hw = reinterpret_cast<uint32_t*>(&hv);
    uint32_t* lw = reinterpret_cast<uint32_t*>(&lv);
#pragma unroll
    for (int p = 0; p < 4; ++p) {
        float a = f[2 * p];
        float b = (2 * p + 1 < 7) ? f[2 * p + 1] : 0.0f;
        hw[p] = split_pair(a, b, lw[p]);
    }
    *reinterpret_cast<uint4*>(&A2h[(size_t)idx * 8]) = hv;
    *reinterpret_cast<uint4*>(&A2l[(size_t)idx * 8]) = lv;
}

// ---------------- Double-buffered fused GEMM --------------------------------
// Stage layout (bytes): Ah[0,PB) Al[PB,2PB) Bh[2PB,3PB) Bl[3PB,4PB); 2 stages.
// K-chunk = 32 feats = 4 input dims.  Loop order: MMAs(c) THEN fill(c+1).
template <int IN, int OUT, bool PRE>
__launch_bounds__(256, 2)
__global__ void kan_mma(const float* __restrict__ X,
                        const __nv_bfloat16* __restrict__ A2h,
                        const __nv_bfloat16* __restrict__ A2l,
                        const __nv_bfloat16* __restrict__ Whi,
                        const __nv_bfloat16* __restrict__ Wlo,
                        float* __restrict__ Y, int nrows) {
    extern __shared__ uint32_t smw[];
    const uint32_t smb = (uint32_t)__cvta_generic_to_shared(smw);

    const int tid  = threadIdx.x;
    const int lane = tid & 31;
    const int wid  = tid >> 5;
    const int wm   = wid & 3;
    const int wn   = wid >> 2;
    const int row0 = blockIdx.x * 128;
    const int KF   = IN * 8;

    int ch0, ch1, col0;
    float* Yb = Y;
    if (PRE) {                          // layer 2: full K, col tile
        ch0 = 0; ch1 = IN / 4;
        col0 = blockIdx.y * 128;
    } else {                            // layer 1: split-K halves
        const int half = (IN / 4) / 2;
        ch0 = blockIdx.y * half; ch1 = ch0 + half;
        col0 = 0;
        Yb = Y + (size_t)blockIdx.y * nrows * OUT;
    }

    // A-fill row mapping (layer 1): 2 scalars per thread
    const int fr = tid >> 1, fhalf = tid & 1;
    int frow = row0 + fr;
    if (frow >= nrows) frow = nrows - 1;

    // ldmatrix base offsets (within a stage)
    const int lt = lane >> 3, lr = lane & 7;
    uint32_t aOff[2], bOff[4];
#pragma unroll
    for (int mt = 0; mt < 2; ++mt) {
        int rowl = wm * 32 + mt * 16 + (lt & 1) * 8 + lr;
        aOff[mt] = (uint32_t)(rowl * PADW + (lt >> 1) * 4) * 4;
    }
#pragma unroll
    for (int ntp = 0; ntp < 4; ++ntp) {
        int nl = wn * 64 + ntp * 16 + (lt >> 1) * 8 + lr;
        bOff[ntp] = 2 * PB + (uint32_t)(nl * PADW + (lt & 1) * 4) * 4;
    }

    // ---- stage fill helper (chunk c -> stage base sOff) ----
    auto fill = [&](int c, uint32_t sOff) {
        const int i0 = c * 4;  // first input dim of chunk
        if (PRE) {
#pragma unroll
            for (int it = 0; it < 2; ++it) {
                int li  = it * 256 + tid;
                int r = li >> 2, j = li & 3;
                int row = row0 + r;
                if (row >= nrows) row = nrows - 1;
                const size_t so = (size_t)row * KF + c * 32 + j * 8;
                uint32_t dw = smb + sOff + (uint32_t)(r * PADW + j * 4) * 4;
                cp_async16(dw, &A2h[so]);
                cp_async16(dw + PB, &A2l[so]);
            }
        } else {
            const float2 xv = *reinterpret_cast<const float2*>(
                &X[(size_t)frow * IN + i0 + fhalf * 2]);
            float xs[2] = {xv.x, xv.y};
            uint32_t* Ah = smw + (sOff >> 2) + fr * PADW;
            uint32_t* Al = Ah + (PB >> 2);
#pragma unroll
            for (int j = 0; j < 2; ++j) {
                float f[7];
                kan_feats(xs[j], f);
                const int d = fhalf * 2 + j;
#pragma unroll
                for (int p = 0; p < 4; ++p) {
                    float a = f[2 * p];
                    float b = (2 * p + 1 < 7) ? f[2 * p + 1] : 0.0f;
                    uint32_t lo, hi = split_pair(a, b, lo);
                    Ah[d * 4 + p] = hi;
                    Al[d * 4 + p] = lo;
                }
            }
        }
#pragma unroll
        for (int it = 0; it < 2; ++it) {
            int li  = it * 256 + tid;
            int r = li >> 2, j = li & 3;
            const size_t so = (size_t)(col0 + r) * KF + c * 32 + j * 8;
            uint32_t dw = smb + sOff + 2 * PB + (uint32_t)(r * PADW + j * 4) * 4;
            cp_async16(dw, &Whi[so]);
            cp_async16(dw + PB, &Wlo[so]);
        }
        cp_commit();
    };

    float acc[2][8][4];
#pragma unroll
    for (int mt = 0; mt < 2; ++mt)
#pragma unroll
        for (int nt = 0; nt < 8; ++nt)
#pragma unroll
            for (int q = 0; q < 4; ++q) acc[mt][nt][q] = 0.0f;

    // ---- prologue: fill stage 0 ----
    fill(ch0, 0);
    cp_wait0();
    __syncthreads();

    for (int c = ch0; c < ch1; ++c) {
        const uint32_t sOff  = (uint32_t)((c - ch0) & 1) * SB;
        const uint32_t sOffN = sOff ^ SB;

        // ---- MMAs FIRST: queue tensor work, then overlap fill under it ----
#pragma unroll
        for (int ks = 0; ks < 2; ++ks) {
            const uint32_t ko = ks * 32;
            uint32_t ah[2][4], al[2][4];
            ldm_x4(ah[0], smb + sOff + aOff[0] + ko);
            ldm_x4(ah[1], smb + sOff + aOff[1] + ko);
            ldm_x4(al[0], smb + sOff + aOff[0] + PB + ko);
            ldm_x4(al[1], smb + sOff + aOff[1] + PB + ko);
#pragma unroll
            for (int ntp = 0; ntp < 4; ++ntp) {
                uint32_t bh[4], bl[4];
                ldm_x4(bh, smb + sOff + bOff[ntp] + ko);
                ldm_x4(bl, smb + sOff + bOff[ntp] + PB + ko);
                // pass-outer: consecutive MMAs hit different accumulators
#pragma unroll
                for (int sub = 0; sub < 2; ++sub)
#pragma unroll
                    for (int mt = 0; mt < 2; ++mt)
                        mma16816(acc[mt][ntp * 2 + sub], ah[mt],
                                 bh[2 * sub], bh[2 * sub + 1]);
#pragma unroll
                for (int sub = 0; sub < 2; ++sub)
#pragma unroll
                    for (int mt = 0; mt < 2; ++mt)
                        mma16816(acc[mt][ntp * 2 + sub], ah[mt],
                                 bl[2 * sub], bl[2 * sub + 1]);
#pragma unroll
                for (int sub = 0; sub < 2; ++sub)
#pragma unroll
                    for (int mt = 0; mt < 2; ++mt)
                        mma16816(acc[mt][ntp * 2 + sub], al[mt],
                                 bh[2 * sub], bh[2 * sub + 1]);
            }
        }

        // ---- fill next chunk while tensor pipe drains ----
        if (c + 1 < ch1) fill(c + 1, sOffN);

        cp_wait0();
        __syncthreads();
    }

    // ---- epilogue ----
    const int g  = lane >> 2;
    const int cq = lane & 3;
#pragma unroll
    for (int mt = 0; mt < 2; ++mt) {
        const int rowA = row0 + wm * 32 + mt * 16 + g;
#pragma unroll
        for (int nt = 0; nt < 8; ++nt) {
            const int col = col0 + wn * 64 + nt * 8 + cq * 2;
            if (rowA < nrows)
                *reinterpret_cast<float2*>(&Yb[(size_t)rowA * OUT + col]) =
                    make_float2(acc[mt][nt][0], acc[mt][nt][1]);
            if (rowA + 8 < nrows)
                *reinterpret_cast<float2*>(&Yb[(size_t)(rowA + 8) * OUT + col]) =
                    make_float2(acc[mt][nt][2], acc[mt][nt][3]);
        }
    }
}

// ---------------------------------------------------------------------------
extern "C" void kernel_launch(void* const* d_in, const int* in_sizes, int n_in,
                              void* d_out, int out_size) {
    const float* x   = (const float*)d_in[0];
    const float* c1  = (const float*)d_in[1];
    const float* sb1 = (const float*)d_in[2];
    const float* sp1 = (const float*)d_in[3];
    const float* c2  = (const float*)d_in[4];
    const float* sb2 = (const float*)d_in[5];
    const float* sp2 = (const float*)d_in[6];
    float* out = (float*)d_out;

    const int nrows = in_sizes[0] / D1;   // 16384
    const int smem  = 2 * SB;             // 81920 B

    __nv_bfloat16 *W1h, *W1l, *W2h, *W2l, *A2h, *A2l;
    float* Y1p;
    cudaGetSymbolAddress((void**)&W1h, g_W1h);
    cudaGetSymbolAddress((void**)&W1l, g_W1l);
    cudaGetSymbolAddress((void**)&W2h, g_W2h);
    cudaGetSymbolAddress((void**)&W2l, g_W2l);
    cudaGetSymbolAddress((void**)&A2h, g_A2h);
    cudaGetSymbolAddress((void**)&A2l, g_A2l);
    cudaGetSymbolAddress((void**)&Y1p, g_y1p);

    cudaFuncSetAttribute((const void*)kan_mma<D1, H1, false>,
                         cudaFuncAttributeMaxDynamicSharedMemorySize, smem);
    cudaFuncSetAttribute((const void*)kan_mma<H1, D1, true>,
                         cudaFuncAttributeMaxDynamicSharedMemorySize, smem);

    prep_wt<D1, H1><<<(D1 * H1 + 255) / 256, 256>>>(c1, sb1, sp1, W1h, W1l);
    prep_wt<H1, D1><<<(H1 * D1 + 255) / 256, 256>>>(c2, sb2, sp2, W2h, W2l);

    const int nrt = (nrows + 127) / 128;
    kan_mma<D1, H1, false><<<dim3(nrt, 2), 256, smem>>>(
        x, nullptr, nullptr, W1h, W1l, Y1p, nrows);
    const int tot = nrows * H1;
    feat2<<<(tot + 255) / 256, 256>>>(Y1p, Y1p + (size_t)nrows * H1, A2h, A2l, tot);
    kan_mma<H1, D1, true><<<dim3(nrt, 8), 256, smem>>>(
        nullptr, A2h, A2l, W2h, W2l, out, nrows);
}

// round 15
// speedup vs baseline: 1.0766x; 1.0766x over previous
#include <cuda_runtime.h>
#include <cuda_bf16.h>
#include <cstdint>

// ============================================================================
// KAN FFN via mma.sync (HMMA) bf16, 2-term split, ldmatrix, double-buffered.
//
// R12 vs R10 (723us):
//  - fill-first loop order restored (R10; R11's MMA-first exposed cp latency)
//  - pass-outer MMA interleave kept (consecutive MMAs hit different accs)
//  - closed-form uniform-grid B-spline featurization in layer-1 fill
//    (~25 instrs/scalar vs ~110 for the Cox-de-Boor recursion)
// ============================================================================

#define D1 1024
#define H1 128
#define MAXROWS 16384
#define PADW 20                   // words per 32-feat row (16 data + 4 pad)
#define PB   (128 * PADW * 4)     // plane bytes (10240)
#define SB   (4 * PB)             // stage bytes  (40960): Ah|Al|Bh|Bl

__device__ __nv_bfloat16 g_W1h[H1 * D1 * 8];
__device__ __nv_bfloat16 g_W1l[H1 * D1 * 8];
__device__ __nv_bfloat16 g_W2h[D1 * H1 * 8];
__device__ __nv_bfloat16 g_W2l[D1 * H1 * 8];
__device__ float g_y1p[2 * MAXROWS * H1];
__device__ __nv_bfloat16 g_A2h[MAXROWS * H1 * 8];
__device__ __nv_bfloat16 g_A2l[MAXROWS * H1 * 8];

// ---------------- KAN featurization, recursion form (feat2 only) ------------
__device__ __forceinline__ void kan_feats(float x, float* f) {
    const float h = 2.0f / 3.0f;
    float B[9];
#pragma unroll
    for (int t = 0; t < 9; ++t) {
        float gl = (float)(t - 3) * h - 1.0f;
        float gr = (float)(t - 2) * h - 1.0f;
        B[t] = (x >= gl && x < gr) ? 1.0f : 0.0f;
    }
#pragma unroll
    for (int d = 1; d <= 3; ++d) {
#pragma unroll
        for (int t = 0; t + d < 9; ++t) {
            float g_t   = (float)(t - 3) * h - 1.0f;
            float g_t1  = (float)(t - 2) * h - 1.0f;
            float g_td  = (float)(t + d - 3) * h - 1.0f;
            float g_td1 = (float)(t + d - 2) * h - 1.0f;
            float inv_l = 1.0f / (g_td - g_t);
            float inv_r = 1.0f / (g_td1 - g_t1);
            B[t] = (x - g_t) * inv_l * B[t] + (g_td1 - x) * inv_r * B[t + 1];
        }
    }
    float sig = 1.0f / (1.0f + __expf(-x));
    f[0] = x * sig;
#pragma unroll
    for (int t = 0; t < 6; ++t) f[1 + t] = B[t];
}

__device__ __forceinline__ uint32_t split_pair(float a, float b, uint32_t& lo) {
    __nv_bfloat16 ah = __float2bfloat16(a), bh = __float2bfloat16(b);
    __nv_bfloat16 al = __float2bfloat16(a - __bfloat162float(ah));
    __nv_bfloat16 bl = __float2bfloat16(b - __bfloat162float(bh));
    lo = (uint32_t)__bfloat16_as_ushort(al) | ((uint32_t)__bfloat16_as_ushort(bl) << 16);
    return (uint32_t)__bfloat16_as_ushort(ah) | ((uint32_t)__bfloat16_as_ushort(bh) << 16);
}

__device__ __forceinline__ void mma16816(float* d, const uint32_t* a,
                                         uint32_t b0, uint32_t b1) {
    asm volatile(
        "mma.sync.aligned.m16n8k16.row.col.f32.bf16.bf16.f32 "
        "{%0,%1,%2,%3}, {%4,%5,%6,%7}, {%8,%9}, {%0,%1,%2,%3};"
        : "+f"(d[0]), "+f"(d[1]), "+f"(d[2]), "+f"(d[3])
        : "r"(a[0]), "r"(a[1]), "r"(a[2]), "r"(a[3]), "r"(b0), "r"(b1));
}

__device__ __forceinline__ void ldm_x4(uint32_t* r, uint32_t addr) {
    asm volatile("ldmatrix.sync.aligned.m8n8.x4.shared.b16 {%0,%1,%2,%3}, [%4];"
                 : "=r"(r[0]), "=r"(r[1]), "=r"(r[2]), "=r"(r[3]) : "r"(addr));
}

__device__ __forceinline__ void cp_async16(uint32_t dst, const void* src) {
    asm volatile("cp.async.cg.shared.global [%0], [%1], 16;"
                 :: "r"(dst), "l"(src) : "memory");
}
__device__ __forceinline__ void cp_commit() {
    asm volatile("cp.async.commit_group;" ::: "memory");
}
__device__ __forceinline__ void cp_wait0() {
    asm volatile("cp.async.wait_group 0;" ::: "memory");
}

// ---------------- Weight prep (unchanged) -----------------------------------
template <int IN, int OUT>
__global__ void prep_wt(const float* __restrict__ coef,
                        const float* __restrict__ sb,
                        const float* __restrict__ sp,
                        __nv_bfloat16* __restrict__ Whi,
                        __nv_bfloat16* __restrict__ Wlo) {
    int idx = blockIdx.x * blockDim.x + threadIdx.x;
    if (idx >= IN * OUT) return;
    int i = idx / OUT, o = idx - i * OUT;
    float vals[8];
    vals[0] = sb[idx];
    float s = sp[idx];
#pragma unroll
    for (int g = 0; g < 6; ++g) vals[1 + g] = coef[(size_t)idx * 6 + g] * s;
    vals[7] = 0.0f;
    size_t base = (size_t)o * (IN * 8) + (size_t)i * 8;
#pragma unroll
    for (int c = 0; c < 8; ++c) {
        float f = vals[c];
        __nv_bfloat16 hb = __float2bfloat16(f);
        Whi[base + c] = hb;
        Wlo[base + c] = __float2bfloat16(f - __bfloat162float(hb));
    }
}

// ---------------- feat2 (unchanged) -----------------------------------------
__global__ void feat2(const float* __restrict__ p0, const float* __restrict__ p1,
                      __nv_bfloat16* __restrict__ A2h,
                      __nv_bfloat16* __restrict__ A2l, int total) {
    int idx = blockIdx.x * blockDim.x + threadIdx.x;
    if (idx >= total) return;
    float y = p0[idx] + p1[idx];
    float f[7];
    kan_feats(y, f);
    uint4 hv, lv;
    uint32_t* hw = reinterpret_cast<uint32_t*>(&hv);
    uint32_t* lw = reinterpret_cast<uint32_t*>(&lv);
#pragma unroll
    for (int p = 0; p < 4; ++p) {
        float a = f[2 * p];
        float b = (2 * p + 1 < 7) ? f[2 * p + 1] : 0.0f;
        hw[p] = split_pair(a, b, lw[p]);
    }
    *reinterpret_cast<uint4*>(&A2h[(size_t)idx * 8]) = hv;
    *reinterpret_cast<uint4*>(&A2l[(size_t)idx * 8]) = lv;
}

// ---------------- Double-buffered fused GEMM --------------------------------
// Stage layout (bytes): Ah[0,PB) Al[PB,2PB) Bh[2PB,3PB) Bl[3PB,4PB); 2 stages.
// K-chunk = 32 feats = 4 input dims.  Loop order: fill(c+1) THEN MMAs(c).
template <int IN, int OUT, bool PRE>
__launch_bounds__(256, 2)
__global__ void kan_mma(const float* __restrict__ X,
                        const __nv_bfloat16* __restrict__ A2h,
                        const __nv_bfloat16* __restrict__ A2l,
                        const __nv_bfloat16* __restrict__ Whi,
                        const __nv_bfloat16* __restrict__ Wlo,
                        float* __restrict__ Y, int nrows) {
    extern __shared__ uint32_t smw[];
    const uint32_t smb = (uint32_t)__cvta_generic_to_shared(smw);

    const int tid  = threadIdx.x;
    const int lane = tid & 31;
    const int wid  = tid >> 5;
    const int wm   = wid & 3;
    const int wn   = wid >> 2;
    const int row0 = blockIdx.x * 128;
    const int KF   = IN * 8;

    int ch0, ch1, col0;
    float* Yb = Y;
    if (PRE) {                          // layer 2: full K, col tile
        ch0 = 0; ch1 = IN / 4;
        col0 = blockIdx.y * 128;
    } else {                            // layer 1: split-K halves
        const int half = (IN / 4) / 2;
        ch0 = blockIdx.y * half; ch1 = ch0 + half;
        col0 = 0;
        Yb = Y + (size_t)blockIdx.y * nrows * OUT;
    }

    // A-fill row mapping (layer 1): 2 scalars per thread
    const int fr = tid >> 1, fhalf = tid & 1;
    int frow = row0 + fr;
    if (frow >= nrows) frow = nrows - 1;

    // ldmatrix base offsets (within a stage)
    const int lt = lane >> 3, lr = lane & 7;
    uint32_t aOff[2], bOff[4];
#pragma unroll
    for (int mt = 0; mt < 2; ++mt) {
        int rowl = wm * 32 + mt * 16 + (lt & 1) * 8 + lr;
        aOff[mt] = (uint32_t)(rowl * PADW + (lt >> 1) * 4) * 4;
    }
#pragma unroll
    for (int ntp = 0; ntp < 4; ++ntp) {
        int nl = wn * 64 + ntp * 16 + (lt >> 1) * 8 + lr;
        bOff[ntp] = 2 * PB + (uint32_t)(nl * PADW + (lt & 1) * 4) * 4;
    }

    // ---- stage fill helper (chunk c -> stage base sOff) ----
    auto fill = [&](int c, uint32_t sOff) {
        const int i0 = c * 4;  // first input dim of chunk
        if (PRE) {
#pragma unroll
            for (int it = 0; it < 2; ++it) {
                int li  = it * 256 + tid;
                int r = li >> 2, j = li & 3;
                int row = row0 + r;
                if (row >= nrows) row = nrows - 1;
                const size_t so = (size_t)row * KF + c * 32 + j * 8;
                uint32_t dw = smb + sOff + (uint32_t)(r * PADW + j * 4) * 4;
                cp_async16(dw, &A2h[so]);
                cp_async16(dw + PB, &A2l[so]);
            }
        } else {
            // closed-form uniform-grid cubic B-spline featurization.
            // knots g_t = (t-3)*(2/3) - 1, t=0..9; for x in [g_m, g_{m+1})
            // nonzero basis j = m-3..m with standard cubic forms in u.
            const float2 xv = *reinterpret_cast<const float2*>(
                &X[(size_t)frow * IN + i0 + fhalf * 2]);
            float xs[2] = {xv.x, xv.y};
            uint32_t* AhW = smw + (sOff >> 2) + fr * PADW;
            uint32_t* AlW = AhW + (PB >> 2);
#pragma unroll
            for (int j = 0; j < 2; ++j) {
                const int d = fhalf * 2 + j;
                const float xx = xs[j];
                // zero 4 hi + 4 lo words (8 feat slots each plane)
                *reinterpret_cast<uint4*>(AhW + d * 4) = make_uint4(0, 0, 0, 0);
                *reinterpret_cast<uint4*>(AlW + d * 4) = make_uint4(0, 0, 0, 0);
                __nv_bfloat16* hb = reinterpret_cast<__nv_bfloat16*>(AhW + d * 4);
                __nv_bfloat16* lb = reinterpret_cast<__nv_bfloat16*>(AlW + d * 4);
                // silu -> slot 0
                float sig = 1.0f / (1.0f + __expf(-xx));
                float s0 = xx * sig;
                __nv_bfloat16 h0 = __float2bfloat16(s0);
                hb[0] = h0;
                lb[0] = __float2bfloat16(s0 - __bfloat162float(h0));
                // splines -> slots 1..6
                float pos = (xx + 3.0f) * 1.5f;
                if (pos >= 0.0f && pos < 9.0f) {
                    int m = (int)pos;          // pos >= 0: trunc == floor
                    float u = pos - (float)m;
                    float u2 = u * u, u3 = u2 * u;
                    float omu = 1.0f - u;
                    float v[4];
                    v[0] = omu * omu * omu * 0.16666667f;
                    v[1] = 0.5f * u3 - u2 + 0.66666667f;
                    v[2] = -0.5f * u3 + 0.5f * u2 + 0.5f * u + 0.16666667f;
                    v[3] = u3 * 0.16666667f;
#pragma unroll
                    for (int k = 0; k < 4; ++k) {
                        int jj = m - 3 + k;
                        if (jj >= 0 && jj <= 5) {
                            __nv_bfloat16 hv = __float2bfloat16(v[k]);
                            hb[jj + 1] = hv;
                            lb[jj + 1] =
                                __float2bfloat16(v[k] - __bfloat162float(hv));
                        }
                    }
                }
            }
        }
#pragma unroll
        for (int it = 0; it < 2; ++it) {
            int li  = it * 256 + tid;
            int r = li >> 2, j = li & 3;
            const size_t so = (size_t)(col0 + r) * KF + c * 32 + j * 8;
            uint32_t dw = smb + sOff + 2 * PB + (uint32_t)(r * PADW + j * 4) * 4;
            cp_async16(dw, &Whi[so]);
            cp_async16(dw + PB, &Wlo[so]);
        }
        cp_commit();
    };

    float acc[2][8][4];
#pragma unroll
    for (int mt = 0; mt < 2; ++mt)
#pragma unroll
        for (int nt = 0; nt < 8; ++nt)
#pragma unroll
            for (int q = 0; q < 4; ++q) acc[mt][nt][q] = 0.0f;

    // ---- prologue: fill stage 0 ----
    fill(ch0, 0);
    cp_wait0();
    __syncthreads();

    for (int c = ch0; c < ch1; ++c) {
        const uint32_t sOff  = (uint32_t)((c - ch0) & 1) * SB;
        const uint32_t sOffN = sOff ^ SB;

        // ---- fill next chunk first: cp latency drains under the MMA phase --
        if (c + 1 < ch1) fill(c + 1, sOffN);

        // ---- MMAs on current stage: pass-outer (acc ILP 4) ----
#pragma unroll
        for (int ks = 0; ks < 2; ++ks) {
            const uint32_t ko = ks * 32;
            uint32_t ah[2][4], al[2][4];
            ldm_x4(ah[0], smb + sOff + aOff[0] + ko);
            ldm_x4(ah[1], smb + sOff + aOff[1] + ko);
            ldm_x4(al[0], smb + sOff + aOff[0] + PB + ko);
            ldm_x4(al[1], smb + sOff + aOff[1] + PB + ko);
#pragma unroll
            for (int ntp = 0; ntp < 4; ++ntp) {
                uint32_t bh[4], bl[4];
                ldm_x4(bh, smb + sOff + bOff[ntp] + ko);
                ldm_x4(bl, smb + sOff + bOff[ntp] + PB + ko);
#pragma unroll
                for (int sub = 0; sub < 2; ++sub)
#pragma unroll
                    for (int mt = 0; mt < 2; ++mt)
                        mma16816(acc[mt][ntp * 2 + sub], ah[mt],
                                 bh[2 * sub], bh[2 * sub + 1]);
#pragma unroll
                for (int sub = 0; sub < 2; ++sub)
#pragma unroll
                    for (int mt = 0; mt < 2; ++mt)
                        mma16816(acc[mt][ntp * 2 + sub], ah[mt],
                                 bl[2 * sub], bl[2 * sub + 1]);
#pragma unroll
                for (int sub = 0; sub < 2; ++sub)
#pragma unroll
                    for (int mt = 0; mt < 2; ++mt)
                        mma16816(acc[mt][ntp * 2 + sub], al[mt],
                                 bh[2 * sub], bh[2 * sub + 1]);
            }
        }

        cp_wait0();
        __syncthreads();
    }

    // ---- epilogue ----
    const int g  = lane >> 2;
    const int cq = lane & 3;
#pragma unroll
    for (int mt = 0; mt < 2; ++mt) {
        const int rowA = row0 + wm * 32 + mt * 16 + g;
#pragma unroll
        for (int nt = 0; nt < 8; ++nt) {
            const int col = col0 + wn * 64 + nt * 8 + cq * 2;
            if (rowA < nrows)
                *reinterpret_cast<float2*>(&Yb[(size_t)rowA * OUT + col]) =
                    make_float2(acc[mt][nt][0], acc[mt][nt][1]);
            if (rowA + 8 < nrows)
                *reinterpret_cast<float2*>(&Yb[(size_t)(rowA + 8) * OUT + col]) =
                    make_float2(acc[mt][nt][2], acc[mt][nt][3]);
        }
    }
}

// ---------------------------------------------------------------------------
extern "C" void kernel_launch(void* const* d_in, const int* in_sizes, int n_in,
                              void* d_out, int out_size) {
    const float* x   = (const float*)d_in[0];
    const float* c1  = (const float*)d_in[1];
    const float* sb1 = (const float*)d_in[2];
    const float* sp1 = (const float*)d_in[3];
    const float* c2  = (const float*)d_in[4];
    const float* sb2 = (const float*)d_in[5];
    const float* sp2 = (const float*)d_in[6];
    float* out = (float*)d_out;

    const int nrows = in_sizes[0] / D1;   // 16384
    const int smem  = 2 * SB;             // 81920 B

    __nv_bfloat16 *W1h, *W1l, *W2h, *W2l, *A2h, *A2l;
    float* Y1p;
    cudaGetSymbolAddress((void**)&W1h, g_W1h);
    cudaGetSymbolAddress((void**)&W1l, g_W1l);
    cudaGetSymbolAddress((void**)&W2h, g_W2h);
    cudaGetSymbolAddress((void**)&W2l, g_W2l);
    cudaGetSymbolAddress((void**)&A2h, g_A2h);
    cudaGetSymbolAddress((void**)&A2l, g_A2l);
    cudaGetSymbolAddress((void**)&Y1p, g_y1p);

    cudaFuncSetAttribute((const void*)kan_mma<D1, H1, false>,
                         cudaFuncAttributeMaxDynamicSharedMemorySize, smem);
    cudaFuncSetAttribute((const void*)kan_mma<H1, D1, true>,
                         cudaFuncAttributeMaxDynamicSharedMemorySize, smem);

    prep_wt<D1, H1><<<(D1 * H1 + 255) / 256, 256>>>(c1, sb1, sp1, W1h, W1l);
    prep_wt<H1, D1><<<(H1 * D1 + 255) / 256, 256>>>(c2, sb2, sp2, W2h, W2l);

    const int nrt = (nrows + 127) / 128;
    kan_mma<D1, H1, false><<<dim3(nrt, 2), 256, smem>>>(
        x, nullptr, nullptr, W1h, W1l, Y1p, nrows);
    const int tot = nrows * H1;
    feat2<<<(tot + 255) / 256, 256>>>(Y1p, Y1p + (size_t)nrows * H1, A2h, A2l, tot);
    kan_mma<H1, D1, true><<<dim3(nrt, 8), 256, smem>>>(
        nullptr, A2h, A2l, W2h, W2l, out, nrows);
}